// round 2
// baseline (speedup 1.0000x reference)
#include <cuda_runtime.h>
#include <math.h>

// Problem constants
#define B_  4
#define T_  2048
#define C_  1024
#define NH_ 16
#define D_  64
#define M_  (B_ * T_)            // 8192 rows
#define INV_TP 0.08838834764831845f   // 1/sqrt(2*D)
#define LN_EPS 1e-5f

// Scratch (device globals; no allocation allowed)
__device__ float g_Q[M_ * C_];
__device__ float g_K[M_ * C_];
__device__ float g_V[M_ * C_];
__device__ float g_A[M_ * C_];

// ---------------------------------------------------------------------------
// GEMM-NT: C[i,j] = sum_k A[i,k] * B[j,k]
// A: [M_ x C_] row-major (x), B: [C_ x C_] row-major (W), C: [M_ x C_]
// Tiles: 128x128x8, 256 threads, 8x8 micro-tile per thread.
// ---------------------------------------------------------------------------
#define GBM 128
#define GBN 128
#define GBK 8

__global__ void __launch_bounds__(256)
gemm_nt_kernel(const float* __restrict__ A, const float* __restrict__ B,
               float* __restrict__ Cm) {
    __shared__ float As[GBK][GBM];
    __shared__ float Bs[GBK][GBN];

    const int tid = threadIdx.x;
    const int tx = tid & 15;          // 0..15 -> col groups of 8
    const int ty = tid >> 4;          // 0..15 -> row groups of 8
    const int bm = blockIdx.y * GBM;
    const int bn = blockIdx.x * GBN;

    const float* Ag = A + (size_t)bm * C_;
    const float* Bg = B + (size_t)bn * C_;

    // load mapping: 256 threads x 1 float4 = 1024 floats = 128 rows x 8 k
    const int lr = tid >> 1;          // row 0..127
    const int lk = (tid & 1) * 4;     // k offset 0 or 4

    float acc[8][8];
    #pragma unroll
    for (int i = 0; i < 8; i++)
        #pragma unroll
        for (int j = 0; j < 8; j++) acc[i][j] = 0.f;

    for (int k0 = 0; k0 < C_; k0 += GBK) {
        float4 a4 = *(const float4*)(Ag + (size_t)lr * C_ + k0 + lk);
        float4 b4 = *(const float4*)(Bg + (size_t)lr * C_ + k0 + lk);
        As[lk + 0][lr] = a4.x; As[lk + 1][lr] = a4.y;
        As[lk + 2][lr] = a4.z; As[lk + 3][lr] = a4.w;
        Bs[lk + 0][lr] = b4.x; Bs[lk + 1][lr] = b4.y;
        Bs[lk + 2][lr] = b4.z; Bs[lk + 3][lr] = b4.w;
        __syncthreads();

        #pragma unroll
        for (int kk = 0; kk < GBK; kk++) {
            float ra[8], rb[8];
            *(float4*)(ra)     = *(const float4*)&As[kk][ty * 8];
            *(float4*)(ra + 4) = *(const float4*)&As[kk][ty * 8 + 4];
            *(float4*)(rb)     = *(const float4*)&Bs[kk][tx * 8];
            *(float4*)(rb + 4) = *(const float4*)&Bs[kk][tx * 8 + 4];
            #pragma unroll
            for (int i = 0; i < 8; i++)
                #pragma unroll
                for (int j = 0; j < 8; j++)
                    acc[i][j] = fmaf(ra[i], rb[j], acc[i][j]);
        }
        __syncthreads();
    }

    #pragma unroll
    for (int i = 0; i < 8; i++) {
        float* crow = Cm + (size_t)(bm + ty * 8 + i) * C_ + bn + tx * 8;
        float4 v0 = make_float4(acc[i][0], acc[i][1], acc[i][2], acc[i][3]);
        float4 v1 = make_float4(acc[i][4], acc[i][5], acc[i][6], acc[i][7]);
        *(float4*)(crow)     = v0;
        *(float4*)(crow + 4) = v1;
    }
}

// ---------------------------------------------------------------------------
// Flash attention (causal), fp32. One block per (query-tile, b*h).
// Tile 64x64, D=64. 128 threads: tx=tid%8 (8 col-groups of 8), ty=tid/8 (16
// row-groups of 4). Online softmax, skip tiles above diagonal.
// ---------------------------------------------------------------------------
#define AT 64
#define APAD 68

__global__ void __launch_bounds__(128)
attn_kernel(const float* __restrict__ Q, const float* __restrict__ K,
            const float* __restrict__ V, float* __restrict__ O_) {
    extern __shared__ float sm[];
    float* Qs = sm;                  // 64 x 68
    float* Ks = Qs + AT * APAD;
    float* Vs = Ks + AT * APAD;
    float* Ps = Vs + AT * APAD;

    const int qt  = blockIdx.x;          // query tile 0..31
    const int bh  = blockIdx.y;          // 0..63
    const int b   = bh / NH_;
    const int h   = bh % NH_;
    const int tid = threadIdx.x;
    const int tx  = tid & 7;             // col / dim group
    const int ty  = tid >> 3;            // row group (0..15)

    const size_t base = ((size_t)b * T_) * C_ + (size_t)h * D_;

    // Load Q tile: 64 rows x 64 dims = 1024 float4
    for (int idx = tid; idx < AT * 16; idx += 128) {
        int r  = idx >> 4;
        int d4 = (idx & 15) * 4;
        *(float4*)&Qs[r * APAD + d4] =
            *(const float4*)(Q + base + (size_t)(qt * AT + r) * C_ + d4);
    }

    float m_i[4], l_i[4], o[4][8];
    #pragma unroll
    for (int i = 0; i < 4; i++) {
        m_i[i] = -1e30f; l_i[i] = 0.f;
        #pragma unroll
        for (int j = 0; j < 8; j++) o[i][j] = 0.f;
    }
    __syncthreads();

    for (int kt = 0; kt <= qt; kt++) {
        // Load K,V tiles
        for (int idx = tid; idx < AT * 16; idx += 128) {
            int r  = idx >> 4;
            int d4 = (idx & 15) * 4;
            const size_t g = base + (size_t)(kt * AT + r) * C_ + d4;
            *(float4*)&Ks[r * APAD + d4] = *(const float4*)(K + g);
            *(float4*)&Vs[r * APAD + d4] = *(const float4*)(V + g);
        }
        __syncthreads();

        // S = Q K^T (64x64), micro-tile 4x8 per thread
        float s[4][8];
        #pragma unroll
        for (int i = 0; i < 4; i++)
            #pragma unroll
            for (int j = 0; j < 8; j++) s[i][j] = 0.f;

        for (int k4 = 0; k4 < AT; k4 += 4) {
            float4 qr[4], kr[8];
            #pragma unroll
            for (int i = 0; i < 4; i++)
                qr[i] = *(const float4*)&Qs[(ty * 4 + i) * APAD + k4];
            #pragma unroll
            for (int j = 0; j < 8; j++)
                kr[j] = *(const float4*)&Ks[(tx * 8 + j) * APAD + k4];
            #pragma unroll
            for (int i = 0; i < 4; i++)
                #pragma unroll
                for (int j = 0; j < 8; j++) {
                    s[i][j] = fmaf(qr[i].x, kr[j].x, s[i][j]);
                    s[i][j] = fmaf(qr[i].y, kr[j].y, s[i][j]);
                    s[i][j] = fmaf(qr[i].z, kr[j].z, s[i][j]);
                    s[i][j] = fmaf(qr[i].w, kr[j].w, s[i][j]);
                }
        }

        // Scale + causal mask (diagonal tile only)
        #pragma unroll
        for (int i = 0; i < 4; i++)
            #pragma unroll
            for (int j = 0; j < 8; j++) {
                float v = s[i][j] * INV_TP;
                if (kt == qt) {
                    int r = ty * 4 + i, c = tx * 8 + j;
                    if (c > r) v = -1e30f;
                }
                s[i][j] = v;
            }

        // Online softmax per row (row spread over 8 tx lanes)
        #pragma unroll
        for (int i = 0; i < 4; i++) {
            float mx = s[i][0];
            #pragma unroll
            for (int j = 1; j < 8; j++) mx = fmaxf(mx, s[i][j]);
            #pragma unroll
            for (int off = 1; off < 8; off <<= 1)
                mx = fmaxf(mx, __shfl_xor_sync(0xffffffffu, mx, off));
            float mnew = fmaxf(m_i[i], mx);
            float corr = __expf(m_i[i] - mnew);
            m_i[i] = mnew;
            float rs = 0.f;
            #pragma unroll
            for (int j = 0; j < 8; j++) {
                float p = __expf(s[i][j] - mnew);
                s[i][j] = p;
                rs += p;
            }
            #pragma unroll
            for (int off = 1; off < 8; off <<= 1)
                rs += __shfl_xor_sync(0xffffffffu, rs, off);
            l_i[i] = l_i[i] * corr + rs;
            #pragma unroll
            for (int j = 0; j < 8; j++) o[i][j] *= corr;
        }

        // Store P to smem
        #pragma unroll
        for (int i = 0; i < 4; i++)
            #pragma unroll
            for (int j = 0; j < 8; j++)
                Ps[(ty * 4 + i) * APAD + tx * 8 + j] = s[i][j];
        __syncthreads();

        // O += P @ V  (rows = same 4, dims d = tx*8..+7)
        for (int c = 0; c < AT; c++) {
            float pr[4];
            #pragma unroll
            for (int i = 0; i < 4; i++) pr[i] = Ps[(ty * 4 + i) * APAD + c];
            float4 v0 = *(const float4*)&Vs[c * APAD + tx * 8];
            float4 v1 = *(const float4*)&Vs[c * APAD + tx * 8 + 4];
            #pragma unroll
            for (int i = 0; i < 4; i++) {
                o[i][0] = fmaf(pr[i], v0.x, o[i][0]);
                o[i][1] = fmaf(pr[i], v0.y, o[i][1]);
                o[i][2] = fmaf(pr[i], v0.z, o[i][2]);
                o[i][3] = fmaf(pr[i], v0.w, o[i][3]);
                o[i][4] = fmaf(pr[i], v1.x, o[i][4]);
                o[i][5] = fmaf(pr[i], v1.y, o[i][5]);
                o[i][6] = fmaf(pr[i], v1.z, o[i][6]);
                o[i][7] = fmaf(pr[i], v1.w, o[i][7]);
            }
        }
        __syncthreads();
    }

    // Normalize and write out
    #pragma unroll
    for (int i = 0; i < 4; i++) {
        float inv = 1.f / l_i[i];
        float* orow = O_ + base + (size_t)(qt * AT + ty * 4 + i) * C_ + tx * 8;
        float4 w0 = make_float4(o[i][0] * inv, o[i][1] * inv, o[i][2] * inv, o[i][3] * inv);
        float4 w1 = make_float4(o[i][4] * inv, o[i][5] * inv, o[i][6] * inv, o[i][7] * inv);
        *(float4*)(orow)     = w0;
        *(float4*)(orow + 4) = w1;
    }
}

// ---------------------------------------------------------------------------
// Residual + LayerNorm. One block per row (8192 blocks, 256 threads).
// ---------------------------------------------------------------------------
__global__ void __launch_bounds__(256)
ln_kernel(const float* __restrict__ x, const float* __restrict__ attn,
          const float* __restrict__ gamma, const float* __restrict__ beta,
          float* __restrict__ out) {
    __shared__ float buf[C_];
    __shared__ float s1[8], s2[8];

    const int row = blockIdx.x;
    const int t = threadIdx.x;                    // 256, one float4 each
    const float4 xa = ((const float4*)(x    + (size_t)row * C_))[t];
    const float4 aa = ((const float4*)(attn + (size_t)row * C_))[t];
    float4 y;
    y.x = xa.x + aa.x; y.y = xa.y + aa.y; y.z = xa.z + aa.z; y.w = xa.w + aa.w;
    ((float4*)buf)[t] = y;

    float lsum = y.x + y.y + y.z + y.w;
    float lsq  = y.x * y.x + y.y * y.y + y.z * y.z + y.w * y.w;
    #pragma unroll
    for (int off = 16; off; off >>= 1) {
        lsum += __shfl_xor_sync(0xffffffffu, lsum, off);
        lsq  += __shfl_xor_sync(0xffffffffu, lsq,  off);
    }
    const int wid = t >> 5, lane = t & 31;
    if (lane == 0) { s1[wid] = lsum; s2[wid] = lsq; }
    __syncthreads();
    if (t == 0) {
        float a = 0.f, b2 = 0.f;
        #pragma unroll
        for (int i = 0; i < 8; i++) { a += s1[i]; b2 += s2[i]; }
        s1[0] = a; s2[0] = b2;
    }
    __syncthreads();
    const float mean = s1[0] * (1.f / C_);
    const float var  = s2[0] * (1.f / C_) - mean * mean;
    const float inv  = rsqrtf(var + LN_EPS);

    const float4 yv = ((const float4*)buf)[t];
    const float4 g  = ((const float4*)gamma)[t];
    const float4 bb = ((const float4*)beta)[t];
    float4 o;
    o.x = (yv.x - mean) * inv * g.x + bb.x;
    o.y = (yv.y - mean) * inv * g.y + bb.y;
    o.z = (yv.z - mean) * inv * g.z + bb.z;
    o.w = (yv.w - mean) * inv * g.w + bb.w;
    ((float4*)(out + (size_t)row * C_))[t] = o;
}

// ---------------------------------------------------------------------------
// Launcher
// ---------------------------------------------------------------------------
extern "C" void kernel_launch(void* const* d_in, const int* in_sizes, int n_in,
                              void* d_out, int out_size) {
    const float* x     = (const float*)d_in[0];
    // d_in[1] = mask (bool) — causal, applied analytically in-kernel
    const float* Wq    = (const float*)d_in[2];
    const float* Wk    = (const float*)d_in[3];
    const float* Wv    = (const float*)d_in[4];
    const float* gamma = (const float*)d_in[5];
    const float* beta  = (const float*)d_in[6];
    float* out = (float*)d_out;

    float *qb, *kb, *vb, *ab;
    cudaGetSymbolAddress((void**)&qb, g_Q);
    cudaGetSymbolAddress((void**)&kb, g_K);
    cudaGetSymbolAddress((void**)&vb, g_V);
    cudaGetSymbolAddress((void**)&ab, g_A);

    dim3 ggrid(C_ / GBN, M_ / GBM);
    gemm_nt_kernel<<<ggrid, 256>>>(x, Wq, qb);
    gemm_nt_kernel<<<ggrid, 256>>>(x, Wk, kb);
    gemm_nt_kernel<<<ggrid, 256>>>(x, Wv, vb);

    const int smem = 4 * AT * APAD * sizeof(float);  // 69632 B
    cudaFuncSetAttribute(attn_kernel, cudaFuncAttributeMaxDynamicSharedMemorySize, smem);
    attn_kernel<<<dim3(T_ / AT, B_ * NH_), 128, smem>>>(qb, kb, vb, ab);

    ln_kernel<<<M_, 256>>>(x, ab, gamma, beta, out);
}

// round 3
// speedup vs baseline: 1.0064x; 1.0064x over previous
#include <cuda_runtime.h>
#include <math.h>

// Problem constants
#define B_  4
#define T_  2048
#define C_  1024
#define NH_ 16
#define D_  64
#define M_  (B_ * T_)            // 8192 rows
#define INV_TP 0.08838834764831845f   // 1/sqrt(2*D)
#define LN_EPS 1e-5f

// Scratch (device globals; no allocation allowed)
__device__ float g_Q[M_ * C_];
__device__ float g_K[M_ * C_];
__device__ float g_V[M_ * C_];
__device__ float g_A[M_ * C_];

// ---------------------------------------------------------------------------
// GEMM-NT: C[i,j] = sum_k A[i,k] * B[j,k]
// A: [M_ x C_] row-major (x), B: [C_ x C_] row-major (W), C: [M_ x C_]
// Tiles: 128x128x8, 256 threads, 8x8 micro-tile per thread.
// ---------------------------------------------------------------------------
#define GBM 128
#define GBN 128
#define GBK 8

__global__ void __launch_bounds__(256)
gemm_nt_kernel(const float* __restrict__ A, const float* __restrict__ B,
               float* __restrict__ Cm) {
    __shared__ float As[GBK][GBM];
    __shared__ float Bs[GBK][GBN];

    const int tid = threadIdx.x;
    const int tx = tid & 15;          // 0..15 -> col groups of 8
    const int ty = tid >> 4;          // 0..15 -> row groups of 8
    const int bm = blockIdx.y * GBM;
    const int bn = blockIdx.x * GBN;

    const float* Ag = A + (size_t)bm * C_;
    const float* Bg = B + (size_t)bn * C_;

    // load mapping: 256 threads x 1 float4 = 1024 floats = 128 rows x 8 k
    const int lr = tid >> 1;          // row 0..127
    const int lk = (tid & 1) * 4;     // k offset 0 or 4

    float acc[8][8];
    #pragma unroll
    for (int i = 0; i < 8; i++)
        #pragma unroll
        for (int j = 0; j < 8; j++) acc[i][j] = 0.f;

    for (int k0 = 0; k0 < C_; k0 += GBK) {
        float4 a4 = *(const float4*)(Ag + (size_t)lr * C_ + k0 + lk);
        float4 b4 = *(const float4*)(Bg + (size_t)lr * C_ + k0 + lk);
        As[lk + 0][lr] = a4.x; As[lk + 1][lr] = a4.y;
        As[lk + 2][lr] = a4.z; As[lk + 3][lr] = a4.w;
        Bs[lk + 0][lr] = b4.x; Bs[lk + 1][lr] = b4.y;
        Bs[lk + 2][lr] = b4.z; Bs[lk + 3][lr] = b4.w;
        __syncthreads();

        #pragma unroll
        for (int kk = 0; kk < GBK; kk++) {
            float ra[8], rb[8];
            *(float4*)(ra)     = *(const float4*)&As[kk][ty * 8];
            *(float4*)(ra + 4) = *(const float4*)&As[kk][ty * 8 + 4];
            *(float4*)(rb)     = *(const float4*)&Bs[kk][tx * 8];
            *(float4*)(rb + 4) = *(const float4*)&Bs[kk][tx * 8 + 4];
            #pragma unroll
            for (int i = 0; i < 8; i++)
                #pragma unroll
                for (int j = 0; j < 8; j++)
                    acc[i][j] = fmaf(ra[i], rb[j], acc[i][j]);
        }
        __syncthreads();
    }

    #pragma unroll
    for (int i = 0; i < 8; i++) {
        float* crow = Cm + (size_t)(bm + ty * 8 + i) * C_ + bn + tx * 8;
        float4 v0 = make_float4(acc[i][0], acc[i][1], acc[i][2], acc[i][3]);
        float4 v1 = make_float4(acc[i][4], acc[i][5], acc[i][6], acc[i][7]);
        *(float4*)(crow)     = v0;
        *(float4*)(crow + 4) = v1;
    }
}

// ---------------------------------------------------------------------------
// Flash attention (causal), fp32. One block per (query-tile, b*h).
// Tile 64x64, D=64. 128 threads: tx=tid%8 (8 col-groups of 8), ty=tid/8 (16
// row-groups of 4). Online softmax, skip tiles above diagonal.
// ---------------------------------------------------------------------------
#define AT 64
#define APAD 68

__global__ void __launch_bounds__(128)
attn_kernel(const float* __restrict__ Q, const float* __restrict__ K,
            const float* __restrict__ V, float* __restrict__ O_) {
    extern __shared__ float sm[];
    float* Qs = sm;                  // 64 x 68
    float* Ks = Qs + AT * APAD;
    float* Vs = Ks + AT * APAD;
    float* Ps = Vs + AT * APAD;

    const int qt  = blockIdx.x;          // query tile 0..31
    const int bh  = blockIdx.y;          // 0..63
    const int b   = bh / NH_;
    const int h   = bh % NH_;
    const int tid = threadIdx.x;
    const int tx  = tid & 7;             // col / dim group
    const int ty  = tid >> 3;            // row group (0..15)

    const size_t base = ((size_t)b * T_) * C_ + (size_t)h * D_;

    // Load Q tile: 64 rows x 64 dims = 1024 float4
    for (int idx = tid; idx < AT * 16; idx += 128) {
        int r  = idx >> 4;
        int d4 = (idx & 15) * 4;
        *(float4*)&Qs[r * APAD + d4] =
            *(const float4*)(Q + base + (size_t)(qt * AT + r) * C_ + d4);
    }

    float m_i[4], l_i[4], o[4][8];
    #pragma unroll
    for (int i = 0; i < 4; i++) {
        m_i[i] = -1e30f; l_i[i] = 0.f;
        #pragma unroll
        for (int j = 0; j < 8; j++) o[i][j] = 0.f;
    }
    __syncthreads();

    for (int kt = 0; kt <= qt; kt++) {
        // Load K,V tiles
        for (int idx = tid; idx < AT * 16; idx += 128) {
            int r  = idx >> 4;
            int d4 = (idx & 15) * 4;
            const size_t g = base + (size_t)(kt * AT + r) * C_ + d4;
            *(float4*)&Ks[r * APAD + d4] = *(const float4*)(K + g);
            *(float4*)&Vs[r * APAD + d4] = *(const float4*)(V + g);
        }
        __syncthreads();

        // S = Q K^T (64x64), micro-tile 4x8 per thread
        float s[4][8];
        #pragma unroll
        for (int i = 0; i < 4; i++)
            #pragma unroll
            for (int j = 0; j < 8; j++) s[i][j] = 0.f;

        for (int k4 = 0; k4 < AT; k4 += 4) {
            float4 qr[4], kr[8];
            #pragma unroll
            for (int i = 0; i < 4; i++)
                qr[i] = *(const float4*)&Qs[(ty * 4 + i) * APAD + k4];
            #pragma unroll
            for (int j = 0; j < 8; j++)
                kr[j] = *(const float4*)&Ks[(tx * 8 + j) * APAD + k4];
            #pragma unroll
            for (int i = 0; i < 4; i++)
                #pragma unroll
                for (int j = 0; j < 8; j++) {
                    s[i][j] = fmaf(qr[i].x, kr[j].x, s[i][j]);
                    s[i][j] = fmaf(qr[i].y, kr[j].y, s[i][j]);
                    s[i][j] = fmaf(qr[i].z, kr[j].z, s[i][j]);
                    s[i][j] = fmaf(qr[i].w, kr[j].w, s[i][j]);
                }
        }

        // Scale + causal mask (diagonal tile only)
        #pragma unroll
        for (int i = 0; i < 4; i++)
            #pragma unroll
            for (int j = 0; j < 8; j++) {
                float v = s[i][j] * INV_TP;
                if (kt == qt) {
                    int r = ty * 4 + i, c = tx * 8 + j;
                    if (c > r) v = -1e30f;
                }
                s[i][j] = v;
            }

        // Online softmax per row (row spread over 8 tx lanes)
        #pragma unroll
        for (int i = 0; i < 4; i++) {
            float mx = s[i][0];
            #pragma unroll
            for (int j = 1; j < 8; j++) mx = fmaxf(mx, s[i][j]);
            #pragma unroll
            for (int off = 1; off < 8; off <<= 1)
                mx = fmaxf(mx, __shfl_xor_sync(0xffffffffu, mx, off));
            float mnew = fmaxf(m_i[i], mx);
            float corr = __expf(m_i[i] - mnew);
            m_i[i] = mnew;
            float rs = 0.f;
            #pragma unroll
            for (int j = 0; j < 8; j++) {
                float p = __expf(s[i][j] - mnew);
                s[i][j] = p;
                rs += p;
            }
            #pragma unroll
            for (int off = 1; off < 8; off <<= 1)
                rs += __shfl_xor_sync(0xffffffffu, rs, off);
            l_i[i] = l_i[i] * corr + rs;
            #pragma unroll
            for (int j = 0; j < 8; j++) o[i][j] *= corr;
        }

        // Store P to smem
        #pragma unroll
        for (int i = 0; i < 4; i++)
            #pragma unroll
            for (int j = 0; j < 8; j++)
                Ps[(ty * 4 + i) * APAD + tx * 8 + j] = s[i][j];
        __syncthreads();

        // O += P @ V  (rows = same 4, dims d = tx*8..+7)
        for (int c = 0; c < AT; c++) {
            float pr[4];
            #pragma unroll
            for (int i = 0; i < 4; i++) pr[i] = Ps[(ty * 4 + i) * APAD + c];
            float4 v0 = *(const float4*)&Vs[c * APAD + tx * 8];
            float4 v1 = *(const float4*)&Vs[c * APAD + tx * 8 + 4];
            #pragma unroll
            for (int i = 0; i < 4; i++) {
                o[i][0] = fmaf(pr[i], v0.x, o[i][0]);
                o[i][1] = fmaf(pr[i], v0.y, o[i][1]);
                o[i][2] = fmaf(pr[i], v0.z, o[i][2]);
                o[i][3] = fmaf(pr[i], v0.w, o[i][3]);
                o[i][4] = fmaf(pr[i], v1.x, o[i][4]);
                o[i][5] = fmaf(pr[i], v1.y, o[i][5]);
                o[i][6] = fmaf(pr[i], v1.z, o[i][6]);
                o[i][7] = fmaf(pr[i], v1.w, o[i][7]);
            }
        }
        __syncthreads();
    }

    // Normalize and write out
    #pragma unroll
    for (int i = 0; i < 4; i++) {
        float inv = 1.f / l_i[i];
        float* orow = O_ + base + (size_t)(qt * AT + ty * 4 + i) * C_ + tx * 8;
        float4 w0 = make_float4(o[i][0] * inv, o[i][1] * inv, o[i][2] * inv, o[i][3] * inv);
        float4 w1 = make_float4(o[i][4] * inv, o[i][5] * inv, o[i][6] * inv, o[i][7] * inv);
        *(float4*)(orow)     = w0;
        *(float4*)(orow + 4) = w1;
    }
}

// ---------------------------------------------------------------------------
// Residual + LayerNorm. One block per row (8192 blocks, 256 threads).
// ---------------------------------------------------------------------------
__global__ void __launch_bounds__(256)
ln_kernel(const float* __restrict__ x, const float* __restrict__ attn,
          const float* __restrict__ gamma, const float* __restrict__ beta,
          float* __restrict__ out) {
    __shared__ float buf[C_];
    __shared__ float s1[8], s2[8];

    const int row = blockIdx.x;
    const int t = threadIdx.x;                    // 256, one float4 each
    const float4 xa = ((const float4*)(x    + (size_t)row * C_))[t];
    const float4 aa = ((const float4*)(attn + (size_t)row * C_))[t];
    float4 y;
    y.x = xa.x + aa.x; y.y = xa.y + aa.y; y.z = xa.z + aa.z; y.w = xa.w + aa.w;
    ((float4*)buf)[t] = y;

    float lsum = y.x + y.y + y.z + y.w;
    float lsq  = y.x * y.x + y.y * y.y + y.z * y.z + y.w * y.w;
    #pragma unroll
    for (int off = 16; off; off >>= 1) {
        lsum += __shfl_xor_sync(0xffffffffu, lsum, off);
        lsq  += __shfl_xor_sync(0xffffffffu, lsq,  off);
    }
    const int wid = t >> 5, lane = t & 31;
    if (lane == 0) { s1[wid] = lsum; s2[wid] = lsq; }
    __syncthreads();
    if (t == 0) {
        float a = 0.f, b2 = 0.f;
        #pragma unroll
        for (int i = 0; i < 8; i++) { a += s1[i]; b2 += s2[i]; }
        s1[0] = a; s2[0] = b2;
    }
    __syncthreads();
    const float mean = s1[0] * (1.f / C_);
    const float var  = s2[0] * (1.f / C_) - mean * mean;
    const float inv  = rsqrtf(var + LN_EPS);

    const float4 yv = ((const float4*)buf)[t];
    const float4 g  = ((const float4*)gamma)[t];
    const float4 bb = ((const float4*)beta)[t];
    float4 o;
    o.x = (yv.x - mean) * inv * g.x + bb.x;
    o.y = (yv.y - mean) * inv * g.y + bb.y;
    o.z = (yv.z - mean) * inv * g.z + bb.z;
    o.w = (yv.w - mean) * inv * g.w + bb.w;
    ((float4*)(out + (size_t)row * C_))[t] = o;
}

// ---------------------------------------------------------------------------
// Launcher
// ---------------------------------------------------------------------------
extern "C" void kernel_launch(void* const* d_in, const int* in_sizes, int n_in,
                              void* d_out, int out_size) {
    const float* x     = (const float*)d_in[0];
    // d_in[1] = mask (bool) — causal, applied analytically in-kernel
    const float* Wq    = (const float*)d_in[2];
    const float* Wk    = (const float*)d_in[3];
    const float* Wv    = (const float*)d_in[4];
    const float* gamma = (const float*)d_in[5];
    const float* beta  = (const float*)d_in[6];
    float* out = (float*)d_out;

    float *qb, *kb, *vb, *ab;
    cudaGetSymbolAddress((void**)&qb, g_Q);
    cudaGetSymbolAddress((void**)&kb, g_K);
    cudaGetSymbolAddress((void**)&vb, g_V);
    cudaGetSymbolAddress((void**)&ab, g_A);

    dim3 ggrid(C_ / GBN, M_ / GBM);
    gemm_nt_kernel<<<ggrid, 256>>>(x, Wq, qb);
    gemm_nt_kernel<<<ggrid, 256>>>(x, Wk, kb);
    gemm_nt_kernel<<<ggrid, 256>>>(x, Wv, vb);

    const int smem = 4 * AT * APAD * sizeof(float);  // 69632 B
    cudaFuncSetAttribute(attn_kernel, cudaFuncAttributeMaxDynamicSharedMemorySize, smem);
    attn_kernel<<<dim3(T_ / AT, B_ * NH_), 128, smem>>>(qb, kb, vb, ab);

    ln_kernel<<<M_, 256>>>(x, ab, gamma, beta, out);
}

// round 4
// speedup vs baseline: 5.4318x; 5.3974x over previous
#include <cuda_runtime.h>
#include <math.h>
#include <stdint.h>

// Problem constants
#define B_  4
#define T_  2048
#define C_  1024
#define NH_ 16
#define D_  64
#define M_  (B_ * T_)                 // 8192 rows
#define INV_TP 0.08838834764831845f  // 1/sqrt(2*D)
#define LN_EPS 1e-5f

// Scratch (device globals; no allocation allowed)
__device__ float g_Q[M_ * C_];
__device__ float g_K[M_ * C_];
__device__ float g_V[M_ * C_];
__device__ float g_A[M_ * C_];

// ---------------------------------------------------------------------------
// Helpers: tf32 convert + m16n8k8 tf32 MMA
// ---------------------------------------------------------------------------
__device__ __forceinline__ uint32_t f2tf(float f) {
    uint32_t u;
    asm("cvt.rna.tf32.f32 %0, %1;" : "=r"(u) : "f"(f));
    return u;
}

__device__ __forceinline__ void mma_tf32(float c[4],
                                         uint32_t a0, uint32_t a1,
                                         uint32_t a2, uint32_t a3,
                                         uint32_t b0, uint32_t b1) {
    asm volatile(
        "mma.sync.aligned.m16n8k8.row.col.f32.tf32.tf32.f32 "
        "{%0,%1,%2,%3},{%4,%5,%6,%7},{%8,%9},{%0,%1,%2,%3};"
        : "+f"(c[0]), "+f"(c[1]), "+f"(c[2]), "+f"(c[3])
        : "r"(a0), "r"(a1), "r"(a2), "r"(a3), "r"(b0), "r"(b1));
}

// ---------------------------------------------------------------------------
// GEMM-NT with tf32 tensor cores: C[m][n] = sum_k A[m][k] * W[n][k]
// Block tile 128x128x32, 256 threads (8 warps, 2x4), warp tile 64x32.
// Smem layout [row][k] pad 36 -> conflict-free scalar fragment loads.
// Register prefetch double-buffers global loads across the k-loop.
// ---------------------------------------------------------------------------
#define BM 128
#define BN 128
#define BK 32
#define KPAD 36

__global__ void __launch_bounds__(256)
gemm_nt_kernel(const float* __restrict__ A, const float* __restrict__ W,
               float* __restrict__ Cm) {
    __shared__ uint32_t As[BM * KPAD];
    __shared__ uint32_t Bs[BN * KPAD];

    const int tid = threadIdx.x;
    const int warp = tid >> 5;
    const int lane = tid & 31;
    const int g = lane >> 2;   // 0..7
    const int q = lane & 3;    // 0..3
    const int wm = (warp & 1) * 64;   // warp M offset (2 warps)
    const int wn = (warp >> 1) * 32;  // warp N offset (4 warps)

    const int bm = blockIdx.y * BM;
    const int bn = blockIdx.x * BN;

    float c[2][4][4];  // [mt 0..3 folded as 2x? no: mt 0..3] -> use [4][4]
    float cc[4][4][4]; // [mt][nt][frag]
    #pragma unroll
    for (int mt = 0; mt < 4; mt++)
        #pragma unroll
        for (int nt = 0; nt < 4; nt++)
            #pragma unroll
            for (int e = 0; e < 4; e++) cc[mt][nt][e] = 0.f;
    (void)c;

    float4 pa[4], pb[4];

    // prefetch k-tile 0
    #pragma unroll
    for (int i = 0; i < 4; i++) {
        int idx = tid + i * 256;
        int m = idx >> 3, kq = idx & 7;
        pa[i] = *(const float4*)(A + (size_t)(bm + m) * C_ + kq * 4);
        pb[i] = *(const float4*)(W + (size_t)(bn + m) * C_ + kq * 4);
    }
    // store tile 0
    #pragma unroll
    for (int i = 0; i < 4; i++) {
        int idx = tid + i * 256;
        int m = idx >> 3, kq = idx & 7;
        uint4 ua = make_uint4(f2tf(pa[i].x), f2tf(pa[i].y), f2tf(pa[i].z), f2tf(pa[i].w));
        uint4 ub = make_uint4(f2tf(pb[i].x), f2tf(pb[i].y), f2tf(pb[i].z), f2tf(pb[i].w));
        *(uint4*)&As[m * KPAD + kq * 4] = ua;
        *(uint4*)&Bs[m * KPAD + kq * 4] = ub;
    }
    __syncthreads();

    const int NT = C_ / BK;  // 32
    for (int kt = 0; kt < NT; kt++) {
        // prefetch next k-tile into registers
        if (kt + 1 < NT) {
            const int k0 = (kt + 1) * BK;
            #pragma unroll
            for (int i = 0; i < 4; i++) {
                int idx = tid + i * 256;
                int m = idx >> 3, kq = idx & 7;
                pa[i] = *(const float4*)(A + (size_t)(bm + m) * C_ + k0 + kq * 4);
                pb[i] = *(const float4*)(W + (size_t)(bn + m) * C_ + k0 + kq * 4);
            }
        }

        // compute: 4 k-steps of 8
        #pragma unroll
        for (int ks = 0; ks < 4; ks++) {
            uint32_t af[4][4];
            #pragma unroll
            for (int mt = 0; mt < 4; mt++) {
                int r = wm + mt * 16;
                af[mt][0] = As[(r + g) * KPAD + ks * 8 + q];
                af[mt][1] = As[(r + g + 8) * KPAD + ks * 8 + q];
                af[mt][2] = As[(r + g) * KPAD + ks * 8 + q + 4];
                af[mt][3] = As[(r + g + 8) * KPAD + ks * 8 + q + 4];
            }
            uint32_t bf[4][2];
            #pragma unroll
            for (int nt = 0; nt < 4; nt++) {
                int n = wn + nt * 8;
                bf[nt][0] = Bs[(n + g) * KPAD + ks * 8 + q];
                bf[nt][1] = Bs[(n + g) * KPAD + ks * 8 + q + 4];
            }
            #pragma unroll
            for (int mt = 0; mt < 4; mt++)
                #pragma unroll
                for (int nt = 0; nt < 4; nt++)
                    mma_tf32(cc[mt][nt], af[mt][0], af[mt][1], af[mt][2], af[mt][3],
                             bf[nt][0], bf[nt][1]);
        }

        if (kt + 1 < NT) {
            __syncthreads();
            #pragma unroll
            for (int i = 0; i < 4; i++) {
                int idx = tid + i * 256;
                int m = idx >> 3, kq = idx & 7;
                uint4 ua = make_uint4(f2tf(pa[i].x), f2tf(pa[i].y), f2tf(pa[i].z), f2tf(pa[i].w));
                uint4 ub = make_uint4(f2tf(pb[i].x), f2tf(pb[i].y), f2tf(pb[i].z), f2tf(pb[i].w));
                *(uint4*)&As[m * KPAD + kq * 4] = ua;
                *(uint4*)&Bs[m * KPAD + kq * 4] = ub;
            }
            __syncthreads();
        }
    }

    // epilogue
    #pragma unroll
    for (int mt = 0; mt < 4; mt++) {
        int r0 = bm + wm + mt * 16 + g;
        #pragma unroll
        for (int nt = 0; nt < 4; nt++) {
            int col = bn + wn + nt * 8 + 2 * q;
            *(float2*)(Cm + (size_t)r0 * C_ + col) =
                make_float2(cc[mt][nt][0], cc[mt][nt][1]);
            *(float2*)(Cm + (size_t)(r0 + 8) * C_ + col) =
                make_float2(cc[mt][nt][2], cc[mt][nt][3]);
        }
    }
}

// ---------------------------------------------------------------------------
// Flash attention (causal) with tf32 tensor cores.
// Tile 64x64, D=64. 128 threads = 4 warps; each warp owns 16 query rows.
// Smem: Qs/Ks/Ps [row][64+4], Vs [row][64+8] (bank-conflict-free frag loads).
// ---------------------------------------------------------------------------
#define QP 68
#define VP 72

__global__ void __launch_bounds__(128)
attn_kernel(const float* __restrict__ Q, const float* __restrict__ K,
            const float* __restrict__ V, float* __restrict__ O_) {
    extern __shared__ uint32_t smu[];
    uint32_t* Qs = smu;             // 64 x 68
    uint32_t* Ks = Qs + 64 * QP;    // 64 x 68
    uint32_t* Vs = Ks + 64 * QP;    // 64 x 72
    uint32_t* Ps = Vs + 64 * VP;    // 64 x 68

    const int qt  = blockIdx.x;  // query tile 0..31
    const int bh  = blockIdx.y;  // 0..63
    const int b   = bh / NH_;
    const int h   = bh % NH_;
    const int tid = threadIdx.x;
    const int warp = tid >> 5;
    const int lane = tid & 31;
    const int g = lane >> 2;
    const int q = lane & 3;
    const int rw = warp * 16;

    const size_t base = ((size_t)b * T_) * C_ + (size_t)h * D_;

    // Load Q tile (tf32 converted)
    for (int i = tid; i < 64 * 16; i += 128) {
        int r = i >> 4, d4 = (i & 15) * 4;
        float4 v = *(const float4*)(Q + base + (size_t)(qt * 64 + r) * C_ + d4);
        *(uint4*)&Qs[r * QP + d4] =
            make_uint4(f2tf(v.x), f2tf(v.y), f2tf(v.z), f2tf(v.w));
    }

    float o[8][4];
    #pragma unroll
    for (int nt = 0; nt < 8; nt++)
        #pragma unroll
        for (int e = 0; e < 4; e++) o[nt][e] = 0.f;
    float m0 = -1e30f, m1 = -1e30f, l0 = 0.f, l1 = 0.f;

    for (int kt = 0; kt <= qt; kt++) {
        // Load K, V tiles (no transpose needed; natural [kv][d] layout)
        for (int i = tid; i < 64 * 16; i += 128) {
            int r = i >> 4, d4 = (i & 15) * 4;
            const size_t gaddr = base + (size_t)(kt * 64 + r) * C_ + d4;
            float4 kv = *(const float4*)(K + gaddr);
            float4 vv = *(const float4*)(V + gaddr);
            *(uint4*)&Ks[r * QP + d4] =
                make_uint4(f2tf(kv.x), f2tf(kv.y), f2tf(kv.z), f2tf(kv.w));
            *(uint4*)&Vs[r * VP + d4] =
                make_uint4(f2tf(vv.x), f2tf(vv.y), f2tf(vv.z), f2tf(vv.w));
        }
        __syncthreads();

        // S = Q K^T for this warp's 16 rows: frags s[8][4]
        float s[8][4];
        #pragma unroll
        for (int nt = 0; nt < 8; nt++)
            #pragma unroll
            for (int e = 0; e < 4; e++) s[nt][e] = 0.f;

        #pragma unroll
        for (int ks = 0; ks < 8; ks++) {
            uint32_t a0 = Qs[(rw + g) * QP + ks * 8 + q];
            uint32_t a1 = Qs[(rw + g + 8) * QP + ks * 8 + q];
            uint32_t a2 = Qs[(rw + g) * QP + ks * 8 + q + 4];
            uint32_t a3 = Qs[(rw + g + 8) * QP + ks * 8 + q + 4];
            #pragma unroll
            for (int nt = 0; nt < 8; nt++) {
                uint32_t b0 = Ks[(nt * 8 + g) * QP + ks * 8 + q];
                uint32_t b1 = Ks[(nt * 8 + g) * QP + ks * 8 + q + 4];
                mma_tf32(s[nt], a0, a1, a2, a3, b0, b1);
            }
        }

        // scale + causal mask (diagonal tile)
        #pragma unroll
        for (int nt = 0; nt < 8; nt++)
            #pragma unroll
            for (int e = 0; e < 4; e++) {
                float v = s[nt][e] * INV_TP;
                if (kt == qt) {
                    int r = rw + g + ((e >= 2) ? 8 : 0);
                    int ccol = nt * 8 + 2 * q + (e & 1);
                    if (ccol > r) v = -1e30f;
                }
                s[nt][e] = v;
            }

        // online softmax: rows r0 (frag e=0,1) and r1 (e=2,3)
        float mx0 = -1e30f, mx1 = -1e30f;
        #pragma unroll
        for (int nt = 0; nt < 8; nt++) {
            mx0 = fmaxf(mx0, fmaxf(s[nt][0], s[nt][1]));
            mx1 = fmaxf(mx1, fmaxf(s[nt][2], s[nt][3]));
        }
        mx0 = fmaxf(mx0, __shfl_xor_sync(0xffffffffu, mx0, 1));
        mx0 = fmaxf(mx0, __shfl_xor_sync(0xffffffffu, mx0, 2));
        mx1 = fmaxf(mx1, __shfl_xor_sync(0xffffffffu, mx1, 1));
        mx1 = fmaxf(mx1, __shfl_xor_sync(0xffffffffu, mx1, 2));

        float mn0 = fmaxf(m0, mx0), mn1 = fmaxf(m1, mx1);
        float corr0 = __expf(m0 - mn0), corr1 = __expf(m1 - mn1);
        m0 = mn0; m1 = mn1;

        float rs0 = 0.f, rs1 = 0.f;
        #pragma unroll
        for (int nt = 0; nt < 8; nt++) {
            float p0 = __expf(s[nt][0] - mn0);
            float p1 = __expf(s[nt][1] - mn0);
            float p2 = __expf(s[nt][2] - mn1);
            float p3 = __expf(s[nt][3] - mn1);
            s[nt][0] = p0; s[nt][1] = p1; s[nt][2] = p2; s[nt][3] = p3;
            rs0 += p0 + p1; rs1 += p2 + p3;
        }
        rs0 += __shfl_xor_sync(0xffffffffu, rs0, 1);
        rs0 += __shfl_xor_sync(0xffffffffu, rs0, 2);
        rs1 += __shfl_xor_sync(0xffffffffu, rs1, 1);
        rs1 += __shfl_xor_sync(0xffffffffu, rs1, 2);
        l0 = l0 * corr0 + rs0;
        l1 = l1 * corr1 + rs1;

        // rescale running O
        #pragma unroll
        for (int nt = 0; nt < 8; nt++) {
            o[nt][0] *= corr0; o[nt][1] *= corr0;
            o[nt][2] *= corr1; o[nt][3] *= corr1;
        }

        // store P (tf32) to this warp's private Ps rows
        #pragma unroll
        for (int nt = 0; nt < 8; nt++) {
            *(uint2*)&Ps[(rw + g) * QP + nt * 8 + 2 * q] =
                make_uint2(f2tf(s[nt][0]), f2tf(s[nt][1]));
            *(uint2*)&Ps[(rw + g + 8) * QP + nt * 8 + 2 * q] =
                make_uint2(f2tf(s[nt][2]), f2tf(s[nt][3]));
        }
        __syncwarp();

        // O += P @ V
        #pragma unroll
        for (int ks = 0; ks < 8; ks++) {
            uint32_t a0 = Ps[(rw + g) * QP + ks * 8 + q];
            uint32_t a1 = Ps[(rw + g + 8) * QP + ks * 8 + q];
            uint32_t a2 = Ps[(rw + g) * QP + ks * 8 + q + 4];
            uint32_t a3 = Ps[(rw + g + 8) * QP + ks * 8 + q + 4];
            #pragma unroll
            for (int nt = 0; nt < 8; nt++) {
                uint32_t b0 = Vs[(ks * 8 + q) * VP + nt * 8 + g];
                uint32_t b1 = Vs[(ks * 8 + q + 4) * VP + nt * 8 + g];
                mma_tf32(o[nt], a0, a1, a2, a3, b0, b1);
            }
        }
        __syncthreads();  // all warps done with Ks/Vs before next tile load
    }

    // epilogue: normalize and store
    float inv0 = 1.f / l0, inv1 = 1.f / l1;
    #pragma unroll
    for (int nt = 0; nt < 8; nt++) {
        int col = nt * 8 + 2 * q;
        *(float2*)(O_ + base + (size_t)(qt * 64 + rw + g) * C_ + col) =
            make_float2(o[nt][0] * inv0, o[nt][1] * inv0);
        *(float2*)(O_ + base + (size_t)(qt * 64 + rw + g + 8) * C_ + col) =
            make_float2(o[nt][2] * inv1, o[nt][3] * inv1);
    }
}

// ---------------------------------------------------------------------------
// Residual + LayerNorm. One block per row (8192 blocks, 256 threads).
// ---------------------------------------------------------------------------
__global__ void __launch_bounds__(256)
ln_kernel(const float* __restrict__ x, const float* __restrict__ attn,
          const float* __restrict__ gamma, const float* __restrict__ beta,
          float* __restrict__ out) {
    __shared__ float buf[C_];
    __shared__ float s1[8], s2[8];

    const int row = blockIdx.x;
    const int t = threadIdx.x;
    const float4 xa = ((const float4*)(x    + (size_t)row * C_))[t];
    const float4 aa = ((const float4*)(attn + (size_t)row * C_))[t];
    float4 y;
    y.x = xa.x + aa.x; y.y = xa.y + aa.y; y.z = xa.z + aa.z; y.w = xa.w + aa.w;
    ((float4*)buf)[t] = y;

    float lsum = y.x + y.y + y.z + y.w;
    float lsq  = y.x * y.x + y.y * y.y + y.z * y.z + y.w * y.w;
    #pragma unroll
    for (int off = 16; off; off >>= 1) {
        lsum += __shfl_xor_sync(0xffffffffu, lsum, off);
        lsq  += __shfl_xor_sync(0xffffffffu, lsq,  off);
    }
    const int wid = t >> 5, lane = t & 31;
    if (lane == 0) { s1[wid] = lsum; s2[wid] = lsq; }
    __syncthreads();
    if (t == 0) {
        float a = 0.f, b2 = 0.f;
        #pragma unroll
        for (int i = 0; i < 8; i++) { a += s1[i]; b2 += s2[i]; }
        s1[0] = a; s2[0] = b2;
    }
    __syncthreads();
    const float mean = s1[0] * (1.f / C_);
    const float var  = s2[0] * (1.f / C_) - mean * mean;
    const float inv  = rsqrtf(var + LN_EPS);

    const float4 yv = ((const float4*)buf)[t];
    const float4 gg = ((const float4*)gamma)[t];
    const float4 bb = ((const float4*)beta)[t];
    float4 oo;
    oo.x = (yv.x - mean) * inv * gg.x + bb.x;
    oo.y = (yv.y - mean) * inv * gg.y + bb.y;
    oo.z = (yv.z - mean) * inv * gg.z + bb.z;
    oo.w = (yv.w - mean) * inv * gg.w + bb.w;
    ((float4*)(out + (size_t)row * C_))[t] = oo;
}

// ---------------------------------------------------------------------------
// Launcher
// ---------------------------------------------------------------------------
extern "C" void kernel_launch(void* const* d_in, const int* in_sizes, int n_in,
                              void* d_out, int out_size) {
    const float* x     = (const float*)d_in[0];
    // d_in[1] = mask (bool) — causal, applied analytically in-kernel
    const float* Wq    = (const float*)d_in[2];
    const float* Wk    = (const float*)d_in[3];
    const float* Wv    = (const float*)d_in[4];
    const float* gamma = (const float*)d_in[5];
    const float* beta  = (const float*)d_in[6];
    float* out = (float*)d_out;

    float *qb, *kb, *vb, *ab;
    cudaGetSymbolAddress((void**)&qb, g_Q);
    cudaGetSymbolAddress((void**)&kb, g_K);
    cudaGetSymbolAddress((void**)&vb, g_V);
    cudaGetSymbolAddress((void**)&ab, g_A);

    dim3 ggrid(C_ / BN, M_ / BM);
    gemm_nt_kernel<<<ggrid, 256>>>(x, Wq, qb);
    gemm_nt_kernel<<<ggrid, 256>>>(x, Wk, kb);
    gemm_nt_kernel<<<ggrid, 256>>>(x, Wv, vb);

    const int smem = (64 * QP * 3 + 64 * VP) * sizeof(uint32_t);  // 70656 B
    static int attr_set = 0;
    cudaFuncSetAttribute(attn_kernel, cudaFuncAttributeMaxDynamicSharedMemorySize, smem);
    (void)attr_set;
    attn_kernel<<<dim3(T_ / 64, B_ * NH_), 128, smem>>>(qb, kb, vb, ab);

    ln_kernel<<<M_, 256>>>(x, ab, gamma, beta, out);
}

// round 5
// speedup vs baseline: 6.6353x; 1.2216x over previous
#include <cuda_runtime.h>
#include <math.h>
#include <stdint.h>

// Problem constants
#define B_  4
#define T_  2048
#define C_  1024
#define NH_ 16
#define D_  64
#define M_  (B_ * T_)                 // 8192 rows
#define INV_TP 0.08838834764831845f  // 1/sqrt(2*D)
#define LN_EPS 1e-5f

// Scratch (device globals; no allocation allowed)
__device__ float g_Q[M_ * C_];
__device__ float g_K[M_ * C_];
__device__ float g_V[M_ * C_];
__device__ float g_A[M_ * C_];

// ---------------------------------------------------------------------------
// Helpers
// ---------------------------------------------------------------------------
__device__ __forceinline__ void mma_tf32(float c[4],
                                         uint32_t a0, uint32_t a1,
                                         uint32_t a2, uint32_t a3,
                                         uint32_t b0, uint32_t b1) {
    asm volatile(
        "mma.sync.aligned.m16n8k8.row.col.f32.tf32.tf32.f32 "
        "{%0,%1,%2,%3},{%4,%5,%6,%7},{%8,%9},{%0,%1,%2,%3};"
        : "+f"(c[0]), "+f"(c[1]), "+f"(c[2]), "+f"(c[3])
        : "r"(a0), "r"(a1), "r"(a2), "r"(a3), "r"(b0), "r"(b1));
}

__device__ __forceinline__ void cp16(uint32_t saddr, const void* gptr) {
    asm volatile("cp.async.cg.shared.global [%0], [%1], 16;"
                 :: "r"(saddr), "l"(gptr));
}
#define CP_COMMIT() asm volatile("cp.async.commit_group;")
#define CP_WAIT1()  asm volatile("cp.async.wait_group 1;")
#define CP_WAIT0()  asm volatile("cp.async.wait_group 0;")

// ---------------------------------------------------------------------------
// Fused QKV GEMM-NT (tf32, raw fp32 operands — MMA truncates mantissa).
// C[m][n] = sum_k A[m][k] * W[n][k].  Block tile 128x128x32, 128 threads
// (4 warps, 64x64 warp tile), cp.async 2-stage smem double buffer.
// blockIdx.z selects Wq/Wk/Wv.
// ---------------------------------------------------------------------------
#define GBM 128
#define GBN 128
#define GBK 32
#define GKP 36            // padded k-width (floats); row stride 144B (16B mult)

__global__ void __launch_bounds__(128)
qkv_kernel(const float* __restrict__ x,
           const float* __restrict__ Wq, const float* __restrict__ Wk,
           const float* __restrict__ Wv,
           float* __restrict__ Qo, float* __restrict__ Ko,
           float* __restrict__ Vo) {
    extern __shared__ float smg[];
    float* As = smg;                       // 2 stages x 128 x 36
    float* Bs = smg + 2 * GBM * GKP;
    const uint32_t As_u = (uint32_t)__cvta_generic_to_shared(As);
    const uint32_t Bs_u = (uint32_t)__cvta_generic_to_shared(Bs);
    const uint32_t* Au = (const uint32_t*)As;
    const uint32_t* Bu = (const uint32_t*)Bs;

    const int z = blockIdx.z;
    const float* W = (z == 0) ? Wq : (z == 1) ? Wk : Wv;
    float* Cm      = (z == 0) ? Qo : (z == 1) ? Ko : Vo;

    const int tid  = threadIdx.x;
    const int warp = tid >> 5;
    const int lane = tid & 31;
    const int g = lane >> 2;
    const int q = lane & 3;
    const int wm = (warp & 1) * 64;
    const int wn = (warp >> 1) * 64;
    const int bm = blockIdx.y * GBM;
    const int bn = blockIdx.x * GBN;

    float cc[4][8][4];
    #pragma unroll
    for (int mt = 0; mt < 4; mt++)
        #pragma unroll
        for (int nt = 0; nt < 8; nt++)
            #pragma unroll
            for (int e = 0; e < 4; e++) cc[mt][nt][e] = 0.f;

    auto copy_tile = [&](int st, int kt) {
        const int k0 = kt * GBK;
        const uint32_t sa = As_u + (uint32_t)(st * GBM * GKP) * 4u;
        const uint32_t sb = Bs_u + (uint32_t)(st * GBM * GKP) * 4u;
        #pragma unroll
        for (int i = 0; i < 8; i++) {
            int idx = i * 128 + tid;
            int r = idx >> 3, c4 = (idx & 7) * 4;
            cp16(sa + (uint32_t)(r * GKP + c4) * 4u,
                 x + (size_t)(bm + r) * C_ + k0 + c4);
            cp16(sb + (uint32_t)(r * GKP + c4) * 4u,
                 W + (size_t)(bn + r) * C_ + k0 + c4);
        }
    };

    const int NT = C_ / GBK;   // 32
    copy_tile(0, 0);
    CP_COMMIT();

    for (int kt = 0; kt < NT; kt++) {
        if (kt + 1 < NT) {
            copy_tile((kt + 1) & 1, kt + 1);
            CP_COMMIT();
            CP_WAIT1();
        } else {
            CP_WAIT0();
        }
        __syncthreads();

        const uint32_t* Ac = Au + (kt & 1) * GBM * GKP;
        const uint32_t* Bc = Bu + (kt & 1) * GBM * GKP;

        #pragma unroll
        for (int ks = 0; ks < 4; ks++) {
            uint32_t af[4][4];
            #pragma unroll
            for (int mt = 0; mt < 4; mt++) {
                int r = wm + mt * 16;
                af[mt][0] = Ac[(r + g) * GKP + ks * 8 + q];
                af[mt][1] = Ac[(r + g + 8) * GKP + ks * 8 + q];
                af[mt][2] = Ac[(r + g) * GKP + ks * 8 + q + 4];
                af[mt][3] = Ac[(r + g + 8) * GKP + ks * 8 + q + 4];
            }
            uint32_t bf[8][2];
            #pragma unroll
            for (int nt = 0; nt < 8; nt++) {
                int n = wn + nt * 8;
                bf[nt][0] = Bc[(n + g) * GKP + ks * 8 + q];
                bf[nt][1] = Bc[(n + g) * GKP + ks * 8 + q + 4];
            }
            #pragma unroll
            for (int mt = 0; mt < 4; mt++)
                #pragma unroll
                for (int nt = 0; nt < 8; nt++)
                    mma_tf32(cc[mt][nt], af[mt][0], af[mt][1], af[mt][2],
                             af[mt][3], bf[nt][0], bf[nt][1]);
        }
        __syncthreads();
    }

    #pragma unroll
    for (int mt = 0; mt < 4; mt++) {
        int r0 = bm + wm + mt * 16 + g;
        #pragma unroll
        for (int nt = 0; nt < 8; nt++) {
            int col = bn + wn + nt * 8 + 2 * q;
            *(float2*)(Cm + (size_t)r0 * C_ + col) =
                make_float2(cc[mt][nt][0], cc[mt][nt][1]);
            *(float2*)(Cm + (size_t)(r0 + 8) * C_ + col) =
                make_float2(cc[mt][nt][2], cc[mt][nt][3]);
        }
    }
}

// ---------------------------------------------------------------------------
// Flash attention (causal), tf32 MMA.
// Q tile 128 rows x D=64, KV tiles 64, 4 warps (32 query rows each, 2 m-tiles).
// Q fragments register-resident (0 LDS for A in the S loop).
// K/V double-buffered via cp.async. P round-trips through smem (raw bits).
// ---------------------------------------------------------------------------
#define PSW 68
#define KSW 68
#define VSW 72

__global__ void __launch_bounds__(128)
attn_kernel(const float* __restrict__ Q, const float* __restrict__ K,
            const float* __restrict__ V, float* __restrict__ O_) {
    extern __shared__ float sma[];
    float* Ps = sma;                       // 128 x 68 (Q staging, then P)
    float* Ks = Ps + 128 * PSW;            // 2 x 64 x 68
    float* Vs = Ks + 2 * 64 * KSW;         // 2 x 64 x 72
    const uint32_t Ks_u = (uint32_t)__cvta_generic_to_shared(Ks);
    const uint32_t Vs_u = (uint32_t)__cvta_generic_to_shared(Vs);
    const uint32_t* Pu = (const uint32_t*)Ps;

    const int qt  = (gridDim.x - 1) - blockIdx.x;   // heavy blocks first
    const int bh  = blockIdx.y;
    const int b   = bh / NH_;
    const int h   = bh % NH_;
    const int tid  = threadIdx.x;
    const int warp = tid >> 5;
    const int lane = tid & 31;
    const int g = lane >> 2;
    const int q = lane & 3;
    const int wr = warp * 32;              // warp's row offset within tile

    const size_t base = ((size_t)b * T_) * C_ + (size_t)h * D_;
    const int gqr = qt * 128;

    auto copy_kv = [&](int st, int kt) {
        const uint32_t sk = Ks_u + (uint32_t)(st * 64 * KSW) * 4u;
        const uint32_t sv = Vs_u + (uint32_t)(st * 64 * VSW) * 4u;
        #pragma unroll
        for (int i = 0; i < 8; i++) {
            int idx = i * 128 + tid;
            int r = idx >> 4, d4 = (idx & 15) * 4;
            const float* gsrc = K + base + (size_t)(kt * 64 + r) * C_ + d4;
            cp16(sk + (uint32_t)(r * KSW + d4) * 4u, gsrc);
            cp16(sv + (uint32_t)(r * VSW + d4) * 4u,
                 V + base + (size_t)(kt * 64 + r) * C_ + d4);
        }
    };

    // kick off KV tile 0 fetch, then stage Q (scaled) through Ps
    copy_kv(0, 0);
    CP_COMMIT();

    for (int i = 0; i < 16; i++) {
        int idx = i * 128 + tid;
        int r = idx >> 4, d4 = (idx & 15) * 4;
        float4 v = *(const float4*)(Q + base + (size_t)(gqr + r) * C_ + d4);
        v.x *= INV_TP; v.y *= INV_TP; v.z *= INV_TP; v.w *= INV_TP;
        *(float4*)&Ps[r * PSW + d4] = v;
    }
    __syncthreads();

    // extract register-resident Q fragments (warp's own 32 rows)
    uint32_t qf[2][8][4];
    #pragma unroll
    for (int mt = 0; mt < 2; mt++) {
        int r = wr + mt * 16;
        #pragma unroll
        for (int ks = 0; ks < 8; ks++) {
            qf[mt][ks][0] = Pu[(r + g) * PSW + ks * 8 + q];
            qf[mt][ks][1] = Pu[(r + g + 8) * PSW + ks * 8 + q];
            qf[mt][ks][2] = Pu[(r + g) * PSW + ks * 8 + q + 4];
            qf[mt][ks][3] = Pu[(r + g + 8) * PSW + ks * 8 + q + 4];
        }
    }
    // (no block sync needed: each warp later overwrites only its own Ps rows)

    float o[2][8][4];
    #pragma unroll
    for (int mt = 0; mt < 2; mt++)
        #pragma unroll
        for (int nt = 0; nt < 8; nt++)
            #pragma unroll
            for (int e = 0; e < 4; e++) o[mt][nt][e] = 0.f;
    float mrow[2][2], lrow[2][2];
    #pragma unroll
    for (int mt = 0; mt < 2; mt++) {
        mrow[mt][0] = -1e30f; mrow[mt][1] = -1e30f;
        lrow[mt][0] = 0.f;    lrow[mt][1] = 0.f;
    }

    const int nkv = 2 * qt + 2;
    for (int kt = 0; kt < nkv; kt++) {
        if (kt + 1 < nkv) {
            copy_kv((kt + 1) & 1, kt + 1);
            CP_COMMIT();
            CP_WAIT1();
        } else {
            CP_WAIT0();
        }
        __syncthreads();

        const uint32_t* Kc = (const uint32_t*)(Ks + (kt & 1) * 64 * KSW);
        const uint32_t* Vc = (const uint32_t*)(Vs + (kt & 1) * 64 * VSW);
        const int c0 = kt * 64;
        const bool active = (c0 <= gqr + wr + 31);

        if (active) {
            // S = Q K^T  (A from registers)
            float s[2][8][4];
            #pragma unroll
            for (int mt = 0; mt < 2; mt++)
                #pragma unroll
                for (int nt = 0; nt < 8; nt++)
                    #pragma unroll
                    for (int e = 0; e < 4; e++) s[mt][nt][e] = 0.f;

            #pragma unroll
            for (int ks = 0; ks < 8; ks++) {
                #pragma unroll
                for (int nt = 0; nt < 8; nt++) {
                    uint32_t b0 = Kc[(nt * 8 + g) * KSW + ks * 8 + q];
                    uint32_t b1 = Kc[(nt * 8 + g) * KSW + ks * 8 + q + 4];
                    mma_tf32(s[0][nt], qf[0][ks][0], qf[0][ks][1],
                             qf[0][ks][2], qf[0][ks][3], b0, b1);
                    mma_tf32(s[1][nt], qf[1][ks][0], qf[1][ks][1],
                             qf[1][ks][2], qf[1][ks][3], b0, b1);
                }
            }

            // causal mask (only when tile straddles the diagonal of any row)
            if (c0 + 63 > gqr + wr) {
                #pragma unroll
                for (int mt = 0; mt < 2; mt++)
                    #pragma unroll
                    for (int nt = 0; nt < 8; nt++)
                        #pragma unroll
                        for (int e = 0; e < 4; e++) {
                            int r = gqr + wr + mt * 16 + g + ((e >= 2) ? 8 : 0);
                            int c = c0 + nt * 8 + 2 * q + (e & 1);
                            if (c > r) s[mt][nt][e] = -1e30f;
                        }
            }

            // online softmax per m-tile (row pair g / g+8)
            #pragma unroll
            for (int mt = 0; mt < 2; mt++) {
                float mx0 = -1e30f, mx1 = -1e30f;
                #pragma unroll
                for (int nt = 0; nt < 8; nt++) {
                    mx0 = fmaxf(mx0, fmaxf(s[mt][nt][0], s[mt][nt][1]));
                    mx1 = fmaxf(mx1, fmaxf(s[mt][nt][2], s[mt][nt][3]));
                }
                mx0 = fmaxf(mx0, __shfl_xor_sync(0xffffffffu, mx0, 1));
                mx0 = fmaxf(mx0, __shfl_xor_sync(0xffffffffu, mx0, 2));
                mx1 = fmaxf(mx1, __shfl_xor_sync(0xffffffffu, mx1, 1));
                mx1 = fmaxf(mx1, __shfl_xor_sync(0xffffffffu, mx1, 2));
                float mn0 = fmaxf(mrow[mt][0], mx0);
                float mn1 = fmaxf(mrow[mt][1], mx1);
                float corr0 = __expf(mrow[mt][0] - mn0);
                float corr1 = __expf(mrow[mt][1] - mn1);
                mrow[mt][0] = mn0; mrow[mt][1] = mn1;

                float rs0 = 0.f, rs1 = 0.f;
                #pragma unroll
                for (int nt = 0; nt < 8; nt++) {
                    float p0 = __expf(s[mt][nt][0] - mn0);
                    float p1 = __expf(s[mt][nt][1] - mn0);
                    float p2 = __expf(s[mt][nt][2] - mn1);
                    float p3 = __expf(s[mt][nt][3] - mn1);
                    s[mt][nt][0] = p0; s[mt][nt][1] = p1;
                    s[mt][nt][2] = p2; s[mt][nt][3] = p3;
                    rs0 += p0 + p1; rs1 += p2 + p3;
                }
                rs0 += __shfl_xor_sync(0xffffffffu, rs0, 1);
                rs0 += __shfl_xor_sync(0xffffffffu, rs0, 2);
                rs1 += __shfl_xor_sync(0xffffffffu, rs1, 1);
                rs1 += __shfl_xor_sync(0xffffffffu, rs1, 2);
                lrow[mt][0] = lrow[mt][0] * corr0 + rs0;
                lrow[mt][1] = lrow[mt][1] * corr1 + rs1;
                #pragma unroll
                for (int nt = 0; nt < 8; nt++) {
                    o[mt][nt][0] *= corr0; o[mt][nt][1] *= corr0;
                    o[mt][nt][2] *= corr1; o[mt][nt][3] *= corr1;
                }
            }

            // stage P (raw float bits) in this warp's Ps rows
            #pragma unroll
            for (int mt = 0; mt < 2; mt++) {
                int r = wr + mt * 16;
                #pragma unroll
                for (int nt = 0; nt < 8; nt++) {
                    *(float2*)&Ps[(r + g) * PSW + nt * 8 + 2 * q] =
                        make_float2(s[mt][nt][0], s[mt][nt][1]);
                    *(float2*)&Ps[(r + g + 8) * PSW + nt * 8 + 2 * q] =
                        make_float2(s[mt][nt][2], s[mt][nt][3]);
                }
            }
            __syncwarp();

            // O += P @ V
            #pragma unroll
            for (int ks = 0; ks < 8; ks++) {
                uint32_t a[2][4];
                #pragma unroll
                for (int mt = 0; mt < 2; mt++) {
                    int r = wr + mt * 16;
                    a[mt][0] = Pu[(r + g) * PSW + ks * 8 + q];
                    a[mt][1] = Pu[(r + g + 8) * PSW + ks * 8 + q];
                    a[mt][2] = Pu[(r + g) * PSW + ks * 8 + q + 4];
                    a[mt][3] = Pu[(r + g + 8) * PSW + ks * 8 + q + 4];
                }
                #pragma unroll
                for (int nt = 0; nt < 8; nt++) {
                    uint32_t b0 = Vc[(ks * 8 + q) * VSW + nt * 8 + g];
                    uint32_t b1 = Vc[(ks * 8 + q + 4) * VSW + nt * 8 + g];
                    mma_tf32(o[0][nt], a[0][0], a[0][1], a[0][2], a[0][3], b0, b1);
                    mma_tf32(o[1][nt], a[1][0], a[1][1], a[1][2], a[1][3], b0, b1);
                }
            }
        }
        __syncthreads();
    }

    // epilogue: normalize and store
    #pragma unroll
    for (int mt = 0; mt < 2; mt++) {
        float inv0 = 1.f / lrow[mt][0];
        float inv1 = 1.f / lrow[mt][1];
        int r0 = gqr + wr + mt * 16 + g;
        #pragma unroll
        for (int nt = 0; nt < 8; nt++) {
            int col = nt * 8 + 2 * q;
            *(float2*)(O_ + base + (size_t)r0 * C_ + col) =
                make_float2(o[mt][nt][0] * inv0, o[mt][nt][1] * inv0);
            *(float2*)(O_ + base + (size_t)(r0 + 8) * C_ + col) =
                make_float2(o[mt][nt][2] * inv1, o[mt][nt][3] * inv1);
        }
    }
}

// ---------------------------------------------------------------------------
// Residual + LayerNorm. One block per row.
// ---------------------------------------------------------------------------
__global__ void __launch_bounds__(256)
ln_kernel(const float* __restrict__ x, const float* __restrict__ attn,
          const float* __restrict__ gamma, const float* __restrict__ beta,
          float* __restrict__ out) {
    __shared__ float buf[C_];
    __shared__ float s1[8], s2[8];

    const int row = blockIdx.x;
    const int t = threadIdx.x;
    const float4 xa = ((const float4*)(x    + (size_t)row * C_))[t];
    const float4 aa = ((const float4*)(attn + (size_t)row * C_))[t];
    float4 y;
    y.x = xa.x + aa.x; y.y = xa.y + aa.y; y.z = xa.z + aa.z; y.w = xa.w + aa.w;
    ((float4*)buf)[t] = y;

    float lsum = y.x + y.y + y.z + y.w;
    float lsq  = y.x * y.x + y.y * y.y + y.z * y.z + y.w * y.w;
    #pragma unroll
    for (int off = 16; off; off >>= 1) {
        lsum += __shfl_xor_sync(0xffffffffu, lsum, off);
        lsq  += __shfl_xor_sync(0xffffffffu, lsq,  off);
    }
    const int wid = t >> 5, lane = t & 31;
    if (lane == 0) { s1[wid] = lsum; s2[wid] = lsq; }
    __syncthreads();
    if (t == 0) {
        float a = 0.f, b2 = 0.f;
        #pragma unroll
        for (int i = 0; i < 8; i++) { a += s1[i]; b2 += s2[i]; }
        s1[0] = a; s2[0] = b2;
    }
    __syncthreads();
    const float mean = s1[0] * (1.f / C_);
    const float var  = s2[0] * (1.f / C_) - mean * mean;
    const float inv  = rsqrtf(var + LN_EPS);

    const float4 yv = ((const float4*)buf)[t];
    const float4 gg = ((const float4*)gamma)[t];
    const float4 bb = ((const float4*)beta)[t];
    float4 oo;
    oo.x = (yv.x - mean) * inv * gg.x + bb.x;
    oo.y = (yv.y - mean) * inv * gg.y + bb.y;
    oo.z = (yv.z - mean) * inv * gg.z + bb.z;
    oo.w = (yv.w - mean) * inv * gg.w + bb.w;
    ((float4*)(out + (size_t)row * C_))[t] = oo;
}

// ---------------------------------------------------------------------------
// Launcher
// ---------------------------------------------------------------------------
extern "C" void kernel_launch(void* const* d_in, const int* in_sizes, int n_in,
                              void* d_out, int out_size) {
    const float* x     = (const float*)d_in[0];
    // d_in[1] = mask (bool) — causal, applied analytically in-kernel
    const float* Wq    = (const float*)d_in[2];
    const float* Wk    = (const float*)d_in[3];
    const float* Wv    = (const float*)d_in[4];
    const float* gamma = (const float*)d_in[5];
    const float* beta  = (const float*)d_in[6];
    float* out = (float*)d_out;

    float *qb, *kb, *vb, *ab;
    cudaGetSymbolAddress((void**)&qb, g_Q);
    cudaGetSymbolAddress((void**)&kb, g_K);
    cudaGetSymbolAddress((void**)&vb, g_V);
    cudaGetSymbolAddress((void**)&ab, g_A);

    const int gemm_smem = 2 * 2 * GBM * GKP * sizeof(float);  // 73728 B
    cudaFuncSetAttribute(qkv_kernel, cudaFuncAttributeMaxDynamicSharedMemorySize,
                         gemm_smem);
    qkv_kernel<<<dim3(C_ / GBN, M_ / GBM, 3), 128, gemm_smem>>>(
        x, Wq, Wk, Wv, qb, kb, vb);

    const int attn_smem = (128 * PSW + 2 * 64 * KSW + 2 * 64 * VSW) * sizeof(float);
    cudaFuncSetAttribute(attn_kernel, cudaFuncAttributeMaxDynamicSharedMemorySize,
                         attn_smem);
    attn_kernel<<<dim3(T_ / 128, B_ * NH_), 128, attn_smem>>>(qb, kb, vb, ab);

    ln_kernel<<<M_, 256>>>(x, ab, gamma, beta, out);
}

// round 6
// speedup vs baseline: 7.4711x; 1.1260x over previous
#include <cuda_runtime.h>
#include <math.h>
#include <stdint.h>

// Problem constants
#define B_  4
#define T_  2048
#define C_  1024
#define NH_ 16
#define D_  64
#define M_  (B_ * T_)                 // 8192 rows
#define INV_TP 0.08838834764831845f  // 1/sqrt(2*D)
#define LOG2E 1.4426950408889634f
#define LN_EPS 1e-5f

// Scratch (device globals; no allocation allowed)
__device__ float g_Q[M_ * C_];
__device__ float g_K[M_ * C_];
__device__ float g_V[M_ * C_];
__device__ float g_A[M_ * C_];

// ---------------------------------------------------------------------------
// Helpers
// ---------------------------------------------------------------------------
__device__ __forceinline__ void mma_tf32(float c[4],
                                         uint32_t a0, uint32_t a1,
                                         uint32_t a2, uint32_t a3,
                                         uint32_t b0, uint32_t b1) {
    asm volatile(
        "mma.sync.aligned.m16n8k8.row.col.f32.tf32.tf32.f32 "
        "{%0,%1,%2,%3},{%4,%5,%6,%7},{%8,%9},{%0,%1,%2,%3};"
        : "+f"(c[0]), "+f"(c[1]), "+f"(c[2]), "+f"(c[3])
        : "r"(a0), "r"(a1), "r"(a2), "r"(a3), "r"(b0), "r"(b1));
}

// ldmatrix on 32-bit data: x4 -> full 16x8 tf32 A-frag, x2 -> 8x8 B-frag
__device__ __forceinline__ void ldsm_x4(uint32_t& r0, uint32_t& r1,
                                        uint32_t& r2, uint32_t& r3,
                                        uint32_t addr) {
    asm volatile("ldmatrix.sync.aligned.m8n8.x4.shared.b16 {%0,%1,%2,%3},[%4];"
                 : "=r"(r0), "=r"(r1), "=r"(r2), "=r"(r3) : "r"(addr));
}
__device__ __forceinline__ void ldsm_x2(uint32_t& r0, uint32_t& r1,
                                        uint32_t addr) {
    asm volatile("ldmatrix.sync.aligned.m8n8.x2.shared.b16 {%0,%1},[%2];"
                 : "=r"(r0), "=r"(r1) : "r"(addr));
}

__device__ __forceinline__ float ex2f(float x) {
    float y;
    asm("ex2.approx.ftz.f32 %0, %1;" : "=f"(y) : "f"(x));
    return y;
}

__device__ __forceinline__ void cp16(uint32_t saddr, const void* gptr) {
    asm volatile("cp.async.cg.shared.global [%0], [%1], 16;"
                 :: "r"(saddr), "l"(gptr));
}
#define CP_COMMIT() asm volatile("cp.async.commit_group;")
#define CP_WAIT1()  asm volatile("cp.async.wait_group 1;")
#define CP_WAIT0()  asm volatile("cp.async.wait_group 0;")

// ---------------------------------------------------------------------------
// Fused QKV GEMM-NT (tf32). C[m][n] = sum_k A[m][k] * W[n][k].
// Block 128x128x32, 128 threads (4 warps, 64x64 warp tile), 2-stage cp.async.
// Fragments via ldmatrix (conflict-free with 36-float row pad).
// ---------------------------------------------------------------------------
#define GBM 128
#define GBN 128
#define GBK 32
#define GKP 36            // padded k-width (floats); 144B row stride

__global__ void __launch_bounds__(128)
qkv_kernel(const float* __restrict__ x,
           const float* __restrict__ Wq, const float* __restrict__ Wk,
           const float* __restrict__ Wv,
           float* __restrict__ Qo, float* __restrict__ Ko,
           float* __restrict__ Vo) {
    extern __shared__ float smg[];
    float* As = smg;                       // 2 stages x 128 x 36
    float* Bs = smg + 2 * GBM * GKP;
    const uint32_t As_u = (uint32_t)__cvta_generic_to_shared(As);
    const uint32_t Bs_u = (uint32_t)__cvta_generic_to_shared(Bs);

    const int z = blockIdx.z;
    const float* W = (z == 0) ? Wq : (z == 1) ? Wk : Wv;
    float* Cm      = (z == 0) ? Qo : (z == 1) ? Ko : Vo;

    const int tid  = threadIdx.x;
    const int warp = tid >> 5;
    const int lane = tid & 31;
    const int g = lane >> 2;
    const int q = lane & 3;
    const int wm = (warp & 1) * 64;
    const int wn = (warp >> 1) * 64;
    const int bm = blockIdx.y * GBM;
    const int bn = blockIdx.x * GBN;

    // per-lane ldmatrix offsets (in floats)
    const uint32_t laneA = (uint32_t)(((lane & 15) * GKP + (lane >> 4) * 4) * 4);
    const uint32_t laneB = (uint32_t)(((lane & 7) * GKP + ((lane >> 3) & 1) * 4) * 4);

    float cc[4][8][4];
    #pragma unroll
    for (int mt = 0; mt < 4; mt++)
        #pragma unroll
        for (int nt = 0; nt < 8; nt++)
            #pragma unroll
            for (int e = 0; e < 4; e++) cc[mt][nt][e] = 0.f;

    auto copy_tile = [&](int st, int kt) {
        const int k0 = kt * GBK;
        const uint32_t sa = As_u + (uint32_t)(st * GBM * GKP) * 4u;
        const uint32_t sb = Bs_u + (uint32_t)(st * GBM * GKP) * 4u;
        #pragma unroll
        for (int i = 0; i < 8; i++) {
            int idx = i * 128 + tid;
            int r = idx >> 3, c4 = (idx & 7) * 4;
            cp16(sa + (uint32_t)(r * GKP + c4) * 4u,
                 x + (size_t)(bm + r) * C_ + k0 + c4);
            cp16(sb + (uint32_t)(r * GKP + c4) * 4u,
                 W + (size_t)(bn + r) * C_ + k0 + c4);
        }
    };

    const int NT = C_ / GBK;   // 32
    copy_tile(0, 0);
    CP_COMMIT();

    for (int kt = 0; kt < NT; kt++) {
        if (kt + 1 < NT) {
            copy_tile((kt + 1) & 1, kt + 1);
            CP_COMMIT();
            CP_WAIT1();
        } else {
            CP_WAIT0();
        }
        __syncthreads();

        const uint32_t a_s = As_u + (uint32_t)((kt & 1) * GBM * GKP) * 4u;
        const uint32_t b_s = Bs_u + (uint32_t)((kt & 1) * GBM * GKP) * 4u;

        #pragma unroll
        for (int ks = 0; ks < 4; ks++) {
            uint32_t af[4][4];
            #pragma unroll
            for (int mt = 0; mt < 4; mt++)
                ldsm_x4(af[mt][0], af[mt][1], af[mt][2], af[mt][3],
                        a_s + (uint32_t)(((wm + mt * 16) * GKP + ks * 8) * 4) + laneA);
            uint32_t bf[8][2];
            #pragma unroll
            for (int nt = 0; nt < 8; nt++)
                ldsm_x2(bf[nt][0], bf[nt][1],
                        b_s + (uint32_t)(((wn + nt * 8) * GKP + ks * 8) * 4) + laneB);
            #pragma unroll
            for (int mt = 0; mt < 4; mt++)
                #pragma unroll
                for (int nt = 0; nt < 8; nt++)
                    mma_tf32(cc[mt][nt], af[mt][0], af[mt][1], af[mt][2],
                             af[mt][3], bf[nt][0], bf[nt][1]);
        }
        __syncthreads();
    }

    #pragma unroll
    for (int mt = 0; mt < 4; mt++) {
        int r0 = bm + wm + mt * 16 + g;
        #pragma unroll
        for (int nt = 0; nt < 8; nt++) {
            int col = bn + wn + nt * 8 + 2 * q;
            *(float2*)(Cm + (size_t)r0 * C_ + col) =
                make_float2(cc[mt][nt][0], cc[mt][nt][1]);
            *(float2*)(Cm + (size_t)(r0 + 8) * C_ + col) =
                make_float2(cc[mt][nt][2], cc[mt][nt][3]);
        }
    }
}

// ---------------------------------------------------------------------------
// Flash attention (causal), tf32 MMA + ldmatrix fragments.
// Q tile 128 x D=64, KV tiles 64, 4 warps (32 query rows each).
// Scores computed in log2 domain (Q pre-scaled by INV_TP*log2e).
// ---------------------------------------------------------------------------
#define PSW 68
#define KSW 68
#define VSW 72

__global__ void __launch_bounds__(128)
attn_kernel(const float* __restrict__ Q, const float* __restrict__ K,
            const float* __restrict__ V, float* __restrict__ O_) {
    extern __shared__ float sma[];
    float* Ps = sma;                       // 128 x 68 (Q staging, then P)
    float* Ks = Ps + 128 * PSW;            // 2 x 64 x 68
    float* Vs = Ks + 2 * 64 * KSW;         // 2 x 64 x 72
    const uint32_t Ps_u = (uint32_t)__cvta_generic_to_shared(Ps);
    const uint32_t Ks_u = (uint32_t)__cvta_generic_to_shared(Ks);
    const uint32_t Vs_u = (uint32_t)__cvta_generic_to_shared(Vs);

    const int qt  = (gridDim.x - 1) - blockIdx.x;   // heavy blocks first
    const int bh  = blockIdx.y;
    const int b   = bh / NH_;
    const int h   = bh % NH_;
    const int tid  = threadIdx.x;
    const int warp = tid >> 5;
    const int lane = tid & 31;
    const int g = lane >> 2;
    const int q = lane & 3;
    const int wr = warp * 32;              // warp's row offset within tile

    const uint32_t laneA = (uint32_t)(((lane & 15) * PSW + (lane >> 4) * 4) * 4);
    const uint32_t laneB = (uint32_t)(((lane & 7) * KSW + ((lane >> 3) & 1) * 4) * 4);

    const size_t base = ((size_t)b * T_) * C_ + (size_t)h * D_;
    const int gqr = qt * 128;

    auto copy_kv = [&](int st, int kt) {
        const uint32_t sk = Ks_u + (uint32_t)(st * 64 * KSW) * 4u;
        const uint32_t sv = Vs_u + (uint32_t)(st * 64 * VSW) * 4u;
        #pragma unroll
        for (int i = 0; i < 8; i++) {
            int idx = i * 128 + tid;
            int r = idx >> 4, d4 = (idx & 15) * 4;
            cp16(sk + (uint32_t)(r * KSW + d4) * 4u,
                 K + base + (size_t)(kt * 64 + r) * C_ + d4);
            cp16(sv + (uint32_t)(r * VSW + d4) * 4u,
                 V + base + (size_t)(kt * 64 + r) * C_ + d4);
        }
    };

    copy_kv(0, 0);
    CP_COMMIT();

    // stage Q scaled into log2 domain
    const float qscale = INV_TP * LOG2E;
    for (int i = 0; i < 16; i++) {
        int idx = i * 128 + tid;
        int r = idx >> 4, d4 = (idx & 15) * 4;
        float4 v = *(const float4*)(Q + base + (size_t)(gqr + r) * C_ + d4);
        v.x *= qscale; v.y *= qscale; v.z *= qscale; v.w *= qscale;
        *(float4*)&Ps[r * PSW + d4] = v;
    }
    __syncthreads();

    // register-resident Q fragments via ldmatrix
    uint32_t qf[2][8][4];
    #pragma unroll
    for (int mt = 0; mt < 2; mt++)
        #pragma unroll
        for (int ks = 0; ks < 8; ks++)
            ldsm_x4(qf[mt][ks][0], qf[mt][ks][1], qf[mt][ks][2], qf[mt][ks][3],
                    Ps_u + (uint32_t)(((wr + mt * 16) * PSW + ks * 8) * 4) + laneA);

    float o[2][8][4];
    #pragma unroll
    for (int mt = 0; mt < 2; mt++)
        #pragma unroll
        for (int nt = 0; nt < 8; nt++)
            #pragma unroll
            for (int e = 0; e < 4; e++) o[mt][nt][e] = 0.f;
    float mrow[2][2], lrow[2][2];
    #pragma unroll
    for (int mt = 0; mt < 2; mt++) {
        mrow[mt][0] = -1e30f; mrow[mt][1] = -1e30f;
        lrow[mt][0] = 0.f;    lrow[mt][1] = 0.f;
    }

    const int nkv = 2 * qt + 2;
    for (int kt = 0; kt < nkv; kt++) {
        if (kt + 1 < nkv) {
            copy_kv((kt + 1) & 1, kt + 1);
            CP_COMMIT();
            CP_WAIT1();
        } else {
            CP_WAIT0();
        }
        __syncthreads();

        const uint32_t k_s = Ks_u + (uint32_t)((kt & 1) * 64 * KSW) * 4u;
        const uint32_t* Vc = (const uint32_t*)(Vs + (kt & 1) * 64 * VSW);
        const int c0 = kt * 64;
        const bool active = (c0 <= gqr + wr + 31);

        if (active) {
            // S = Q K^T (A in registers, B via ldmatrix)
            float s[2][8][4];
            #pragma unroll
            for (int mt = 0; mt < 2; mt++)
                #pragma unroll
                for (int nt = 0; nt < 8; nt++)
                    #pragma unroll
                    for (int e = 0; e < 4; e++) s[mt][nt][e] = 0.f;

            #pragma unroll
            for (int ks = 0; ks < 8; ks++) {
                #pragma unroll
                for (int nt = 0; nt < 8; nt++) {
                    uint32_t b0, b1;
                    ldsm_x2(b0, b1,
                            k_s + (uint32_t)(((nt * 8) * KSW + ks * 8) * 4) + laneB);
                    mma_tf32(s[0][nt], qf[0][ks][0], qf[0][ks][1],
                             qf[0][ks][2], qf[0][ks][3], b0, b1);
                    mma_tf32(s[1][nt], qf[1][ks][0], qf[1][ks][1],
                             qf[1][ks][2], qf[1][ks][3], b0, b1);
                }
            }

            // causal mask (tiles straddling the diagonal)
            if (c0 + 63 > gqr + wr) {
                #pragma unroll
                for (int mt = 0; mt < 2; mt++)
                    #pragma unroll
                    for (int nt = 0; nt < 8; nt++)
                        #pragma unroll
                        for (int e = 0; e < 4; e++) {
                            int r = gqr + wr + mt * 16 + g + ((e >= 2) ? 8 : 0);
                            int c = c0 + nt * 8 + 2 * q + (e & 1);
                            if (c > r) s[mt][nt][e] = -1e30f;
                        }
            }

            // online softmax (log2 domain)
            #pragma unroll
            for (int mt = 0; mt < 2; mt++) {
                float mx0 = -1e30f, mx1 = -1e30f;
                #pragma unroll
                for (int nt = 0; nt < 8; nt++) {
                    mx0 = fmaxf(mx0, fmaxf(s[mt][nt][0], s[mt][nt][1]));
                    mx1 = fmaxf(mx1, fmaxf(s[mt][nt][2], s[mt][nt][3]));
                }
                mx0 = fmaxf(mx0, __shfl_xor_sync(0xffffffffu, mx0, 1));
                mx0 = fmaxf(mx0, __shfl_xor_sync(0xffffffffu, mx0, 2));
                mx1 = fmaxf(mx1, __shfl_xor_sync(0xffffffffu, mx1, 1));
                mx1 = fmaxf(mx1, __shfl_xor_sync(0xffffffffu, mx1, 2));
                float mn0 = fmaxf(mrow[mt][0], mx0);
                float mn1 = fmaxf(mrow[mt][1], mx1);
                float corr0 = ex2f(mrow[mt][0] - mn0);
                float corr1 = ex2f(mrow[mt][1] - mn1);
                mrow[mt][0] = mn0; mrow[mt][1] = mn1;

                float rs0 = 0.f, rs1 = 0.f;
                #pragma unroll
                for (int nt = 0; nt < 8; nt++) {
                    float p0 = ex2f(s[mt][nt][0] - mn0);
                    float p1 = ex2f(s[mt][nt][1] - mn0);
                    float p2 = ex2f(s[mt][nt][2] - mn1);
                    float p3 = ex2f(s[mt][nt][3] - mn1);
                    s[mt][nt][0] = p0; s[mt][nt][1] = p1;
                    s[mt][nt][2] = p2; s[mt][nt][3] = p3;
                    rs0 += p0 + p1; rs1 += p2 + p3;
                }
                rs0 += __shfl_xor_sync(0xffffffffu, rs0, 1);
                rs0 += __shfl_xor_sync(0xffffffffu, rs0, 2);
                rs1 += __shfl_xor_sync(0xffffffffu, rs1, 1);
                rs1 += __shfl_xor_sync(0xffffffffu, rs1, 2);
                lrow[mt][0] = lrow[mt][0] * corr0 + rs0;
                lrow[mt][1] = lrow[mt][1] * corr1 + rs1;
                #pragma unroll
                for (int nt = 0; nt < 8; nt++) {
                    o[mt][nt][0] *= corr0; o[mt][nt][1] *= corr0;
                    o[mt][nt][2] *= corr1; o[mt][nt][3] *= corr1;
                }
            }

            // stage P in this warp's Ps rows
            #pragma unroll
            for (int mt = 0; mt < 2; mt++) {
                int r = wr + mt * 16;
                #pragma unroll
                for (int nt = 0; nt < 8; nt++) {
                    *(float2*)&Ps[(r + g) * PSW + nt * 8 + 2 * q] =
                        make_float2(s[mt][nt][0], s[mt][nt][1]);
                    *(float2*)&Ps[(r + g + 8) * PSW + nt * 8 + 2 * q] =
                        make_float2(s[mt][nt][2], s[mt][nt][3]);
                }
            }
            __syncwarp();

            // O += P @ V (A via ldmatrix from Ps, B scalar from Vs)
            #pragma unroll
            for (int ks = 0; ks < 8; ks++) {
                uint32_t a[2][4];
                #pragma unroll
                for (int mt = 0; mt < 2; mt++)
                    ldsm_x4(a[mt][0], a[mt][1], a[mt][2], a[mt][3],
                            Ps_u + (uint32_t)(((wr + mt * 16) * PSW + ks * 8) * 4) + laneA);
                #pragma unroll
                for (int nt = 0; nt < 8; nt++) {
                    uint32_t b0 = Vc[(ks * 8 + q) * VSW + nt * 8 + g];
                    uint32_t b1 = Vc[(ks * 8 + q + 4) * VSW + nt * 8 + g];
                    mma_tf32(o[0][nt], a[0][0], a[0][1], a[0][2], a[0][3], b0, b1);
                    mma_tf32(o[1][nt], a[1][0], a[1][1], a[1][2], a[1][3], b0, b1);
                }
            }
        }
        __syncthreads();
    }

    // epilogue: normalize and store
    #pragma unroll
    for (int mt = 0; mt < 2; mt++) {
        float inv0 = 1.f / lrow[mt][0];
        float inv1 = 1.f / lrow[mt][1];
        int r0 = gqr + wr + mt * 16 + g;
        #pragma unroll
        for (int nt = 0; nt < 8; nt++) {
            int col = nt * 8 + 2 * q;
            *(float2*)(O_ + base + (size_t)r0 * C_ + col) =
                make_float2(o[mt][nt][0] * inv0, o[mt][nt][1] * inv0);
            *(float2*)(O_ + base + (size_t)(r0 + 8) * C_ + col) =
                make_float2(o[mt][nt][2] * inv1, o[mt][nt][3] * inv1);
        }
    }
}

// ---------------------------------------------------------------------------
// Residual + LayerNorm. One block per row.
// ---------------------------------------------------------------------------
__global__ void __launch_bounds__(256)
ln_kernel(const float* __restrict__ x, const float* __restrict__ attn,
          const float* __restrict__ gamma, const float* __restrict__ beta,
          float* __restrict__ out) {
    __shared__ float buf[C_];
    __shared__ float s1[8], s2[8];

    const int row = blockIdx.x;
    const int t = threadIdx.x;
    const float4 xa = ((const float4*)(x    + (size_t)row * C_))[t];
    const float4 aa = ((const float4*)(attn + (size_t)row * C_))[t];
    float4 y;
    y.x = xa.x + aa.x; y.y = xa.y + aa.y; y.z = xa.z + aa.z; y.w = xa.w + aa.w;
    ((float4*)buf)[t] = y;

    float lsum = y.x + y.y + y.z + y.w;
    float lsq  = y.x * y.x + y.y * y.y + y.z * y.z + y.w * y.w;
    #pragma unroll
    for (int off = 16; off; off >>= 1) {
        lsum += __shfl_xor_sync(0xffffffffu, lsum, off);
        lsq  += __shfl_xor_sync(0xffffffffu, lsq,  off);
    }
    const int wid = t >> 5, lane = t & 31;
    if (lane == 0) { s1[wid] = lsum; s2[wid] = lsq; }
    __syncthreads();
    if (t == 0) {
        float a = 0.f, b2 = 0.f;
        #pragma unroll
        for (int i = 0; i < 8; i++) { a += s1[i]; b2 += s2[i]; }
        s1[0] = a; s2[0] = b2;
    }
    __syncthreads();
    const float mean = s1[0] * (1.f / C_);
    const float var  = s2[0] * (1.f / C_) - mean * mean;
    const float inv  = rsqrtf(var + LN_EPS);

    const float4 yv = ((const float4*)buf)[t];
    const float4 gg = ((const float4*)gamma)[t];
    const float4 bb = ((const float4*)beta)[t];
    float4 oo;
    oo.x = (yv.x - mean) * inv * gg.x + bb.x;
    oo.y = (yv.y - mean) * inv * gg.y + bb.y;
    oo.z = (yv.z - mean) * inv * gg.z + bb.z;
    oo.w = (yv.w - mean) * inv * gg.w + bb.w;
    ((float4*)(out + (size_t)row * C_))[t] = oo;
}

// ---------------------------------------------------------------------------
// Launcher
// ---------------------------------------------------------------------------
extern "C" void kernel_launch(void* const* d_in, const int* in_sizes, int n_in,
                              void* d_out, int out_size) {
    const float* x     = (const float*)d_in[0];
    // d_in[1] = mask (bool) — causal, applied analytically in-kernel
    const float* Wq    = (const float*)d_in[2];
    const float* Wk    = (const float*)d_in[3];
    const float* Wv    = (const float*)d_in[4];
    const float* gamma = (const float*)d_in[5];
    const float* beta  = (const float*)d_in[6];
    float* out = (float*)d_out;

    float *qb, *kb, *vb, *ab;
    cudaGetSymbolAddress((void**)&qb, g_Q);
    cudaGetSymbolAddress((void**)&kb, g_K);
    cudaGetSymbolAddress((void**)&vb, g_V);
    cudaGetSymbolAddress((void**)&ab, g_A);

    const int gemm_smem = 2 * 2 * GBM * GKP * sizeof(float);  // 73728 B
    cudaFuncSetAttribute(qkv_kernel, cudaFuncAttributeMaxDynamicSharedMemorySize,
                         gemm_smem);
    qkv_kernel<<<dim3(C_ / GBN, M_ / GBM, 3), 128, gemm_smem>>>(
        x, Wq, Wk, Wv, qb, kb, vb);

    const int attn_smem = (128 * PSW + 2 * 64 * KSW + 2 * 64 * VSW) * sizeof(float);
    cudaFuncSetAttribute(attn_kernel, cudaFuncAttributeMaxDynamicSharedMemorySize,
                         attn_smem);
    attn_kernel<<<dim3(T_ / 128, B_ * NH_), 128, attn_smem>>>(qb, kb, vb, ab);

    ln_kernel<<<M_, 256>>>(x, ab, gamma, beta, out);
}